// round 8
// baseline (speedup 1.0000x reference)
#include <cuda_runtime.h>
#include <stdint.h>
#include <math.h>

// ---------------------------------------------------------------------------
// TripletLossWithCurvature: B=8192, D=512, classes<100
// Bit-exact JAX Threefry-2x32 (partitionable mode). R8: pipe-balanced Threefry
// (adds->IMAD, alternate rotates->IMAD.WIDE+LOP3 via opaque 'one' kernel
// param), compile-time subkeys, simplified per-thread argmax in k_neg.
// ---------------------------------------------------------------------------
#define BB 8192
#define DD 512
#define NCLS 128

__device__ float g_S[DD*DD];
__device__ float g_G[DD*DD];
__device__ float g_H[BB*DD];
__device__ float g_q[BB];
__device__ float g_musum[DD];
__device__ int   g_lab[BB];
__device__ unsigned char g_lab8[BB];
__device__ int   g_cnt[NCLS];
__device__ int   g_off[NCLS];
__device__ int   g_fill[NCLS];
__device__ int   g_list[BB];
__device__ int   g_pos[BB];
__device__ int   g_neg[BB];
__device__ float g_acc[2];

// ---------------------------------------------------------------------------
// Packed fp32 helpers (exact per-lane IEEE fp32)
// ---------------------------------------------------------------------------
__device__ __forceinline__ void ffma2(unsigned long long &acc,
                                      unsigned long long a2,
                                      unsigned long long b2) {
  asm("fma.rn.f32x2 %0, %1, %2, %0;" : "+l"(acc) : "l"(a2), "l"(b2));
}
__device__ __forceinline__ unsigned long long pack2(float x) {
  unsigned long long r;
  unsigned int xi = __float_as_uint(x);
  asm("mov.b64 %0, {%1, %1};" : "=l"(r) : "r"(xi));
  return r;
}
union U64F2 { unsigned long long u; float2 f; };

// ---------------------------------------------------------------------------
// Threefry-2x32 — compile-time subkey derivation (constexpr full block)
// ---------------------------------------------------------------------------
struct K2 { uint32_t a, b; };
constexpr uint32_t c_rotl(uint32_t x, int r) {
  return (x << r) | (x >> (32 - r));
}
constexpr K2 tf_pair(uint32_t k0, uint32_t k1, uint32_t c0, uint32_t c1) {
  uint32_t ks2 = k0 ^ k1 ^ 0x1BD11BDAu;
  uint32_t x0 = c0 + k0, x1 = c1 + k1;
#define CR(r) x0 += x1; x1 = c_rotl(x1, r); x1 ^= x0;
  CR(13) CR(15) CR(26) CR(6)
  x0 += k1;  x1 += ks2 + 1u;
  CR(17) CR(29) CR(16) CR(24)
  x0 += ks2; x1 += k0 + 2u;
  CR(13) CR(15) CR(26) CR(6)
  x0 += k0;  x1 += k1 + 3u;
  CR(17) CR(29) CR(16) CR(24)
  x0 += k1;  x1 += ks2 + 4u;
  CR(13) CR(15) CR(26) CR(6)
  x0 += ks2; x1 += k0 + 5u;
#undef CR
  return K2{x0, x1};
}
// split(key(42)) -> subkeys (partitionable mode: block on count 0 / 1)
constexpr K2 KP = tf_pair(0u, 42u, 0u, 0u);   // positive-sampling key
constexpr K2 KN = tf_pair(0u, 42u, 0u, 1u);   // negative-sampling key

// Pipe-balanced Threefry draw. 'one' is a runtime-opaque 1 (kernel param) so
// ptxas keeps IMAD / IMAD.WIDE instead of strength-reducing to alu-pipe ops.
// mW* = one << {15,6,29,24}. Wide-rotate: rotl(x,r) = lo(x*2^r) | hi(x*2^r);
// the (lo|hi)^x0 is a single 3-input LOP3.
__device__ __forceinline__ uint32_t draw_fast(
    uint32_t k0, uint32_t k1, uint32_t p,
    uint32_t one, uint32_t m15, uint32_t m6, uint32_t m29, uint32_t m24) {
  uint32_t ks2 = k0 ^ k1 ^ 0x1BD11BDAu;
  uint32_t x0 = k0, x1 = p + k1;
#define ADDI(d, s) asm("mad.lo.u32 %0, %1, %2, %0;" : "+r"(d) : "r"(s), "r"(one))
#define RS(r) { ADDI(x0, x1); x1 = __funnelshift_l(x1, x1, r) ^ x0; }
#define RW(m) { ADDI(x0, x1); unsigned long long t = (unsigned long long)x1 * (m); \
                x1 = (((uint32_t)t) | ((uint32_t)(t >> 32))) ^ x0; }
  RS(13) RW(m15) RS(26) RW(m6)
  ADDI(x0, k1);  x1 += ks2 + 1u;
  RS(17) RW(m29) RS(16) RW(m24)
  ADDI(x0, ks2); x1 += k0 + 2u;
  RS(13) RW(m15) RS(26) RW(m6)
  ADDI(x0, k0);  x1 += k1 + 3u;
  RS(17) RW(m29) RS(16) RW(m24)
  ADDI(x0, k1);  x1 += ks2 + 4u;
  RS(13) RW(m15) RS(26) RW(m6)
  ADDI(x0, ks2); x1 += k0 + 5u;
#undef RS
#undef RW
#undef ADDI
  return x0 ^ x1;
}

// ---------------------------------------------------------------------------
// Kernels
// ---------------------------------------------------------------------------
__global__ void k_zero() {
  int idx = blockIdx.x * blockDim.x + threadIdx.x;
  int stride = gridDim.x * blockDim.x;
  for (int i = idx; i < DD*DD; i += stride) g_S[i] = 0.f;
  if (idx < DD) g_musum[idx] = 0.f;
}

__global__ void k_labels(const void* __restrict__ lraw) {
  __shared__ int s_is64;
  if (threadIdx.x < NCLS) g_cnt[threadIdx.x] = 0;
  if (threadIdx.x < 2)    g_acc[threadIdx.x] = 0.f;
  if (threadIdx.x == 0)   s_is64 = 1;
  __syncthreads();
  const int* w = (const int*)lraw;
  int any = 0;
  for (int k = threadIdx.x; k < 4096; k += 1024)
    if (w[2*k + 1] != 0) any = 1;
  if (any) s_is64 = 0;
  __syncthreads();
  int is64 = s_is64;
  for (int i = threadIdx.x; i < BB; i += 1024) {
    int lab = is64 ? (int)(((const long long*)lraw)[i]) : w[i];
    if (lab < 0) lab = 0;
    if (lab >= NCLS) lab = NCLS - 1;
    g_lab[i]  = lab;
    g_lab8[i] = (unsigned char)lab;
    atomicAdd(&g_cnt[lab], 1);
  }
}

__global__ void k_offsets() {
  if (threadIdx.x == 0 && blockIdx.x == 0) {
    int acc = 0;
    for (int c = 0; c < NCLS; c++) { g_off[c] = acc; g_fill[c] = acc; acc += g_cnt[c]; }
  }
}

__global__ void k_scatter() {
  int i = blockIdx.x * blockDim.x + threadIdx.x;
  if (i < BB) {
    int lab = g_lab[i];
    int p = atomicAdd(&g_fill[lab], 1);
    g_list[p] = i;
  }
}

// Positive sampling: one warp per row; g_list is unsorted so keep full
// tie-break logic in the lane loop.
__global__ void k_pos(uint32_t one) {
  uint32_t m15 = one << 15, m6 = one << 6, m29 = one << 29, m24 = one << 24;
  int w = (blockIdx.x * blockDim.x + threadIdx.x) >> 5;
  int lane = threadIdx.x & 31;
  if (w >= BB) return;
  int i = w;
  int lab = g_lab[i];
  int off = g_off[lab], cnt = g_cnt[lab];
  uint32_t base = (uint32_t)i * (uint32_t)BB;
  uint32_t bestv = 0u; int bestj = 0; int any = 0;
  for (int c = lane; c < cnt; c += 32) {
    int j = g_list[off + c];
    if (j == i) continue;
    uint32_t v = draw_fast(KP.a, KP.b, base + (uint32_t)j, one, m15, m6, m29, m24) >> 9;
    if (!any || v > bestv || (v == bestv && j < bestj)) { any = 1; bestv = v; bestj = j; }
  }
  for (int o = 16; o; o >>= 1) {
    uint32_t ov = __shfl_down_sync(0xffffffffu, bestv, o);
    int      oj = __shfl_down_sync(0xffffffffu, bestj, o);
    int      oa = __shfl_down_sync(0xffffffffu, any,  o);
    if (oa && (!any || ov > bestv || (ov == bestv && oj < bestj))) {
      any = 1; bestv = ov; bestj = oj;
    }
  }
  if (lane == 0) g_pos[i] = bestj;
}

// Negative sampling: one block per row. Per-thread j strictly increases, so
// first-max (v > bestv) suffices; ties resolved in the cross-thread reduce.
__global__ void k_neg(uint32_t one) {
  __shared__ unsigned char slab[BB];
  __shared__ uint32_t sv[256];
  __shared__ int sj[256];
  uint32_t m15 = one << 15, m6 = one << 6, m29 = one << 29, m24 = one << 24;
  int i = blockIdx.x, t = threadIdx.x;
  {
    const uint32_t* l4 = (const uint32_t*)g_lab8;
    uint32_t* s4 = (uint32_t*)slab;
    for (int j = t; j < BB / 4; j += 256) s4[j] = l4[j];
  }
  __syncthreads();
  unsigned char mylab = slab[i];
  uint32_t base = (uint32_t)i * (uint32_t)BB;
  uint32_t bestv = 0u; int bestj = -1;
  for (int j = t; j < BB; j += 256) {
    if (slab[j] == mylab) continue;
    uint32_t v = draw_fast(KN.a, KN.b, base + (uint32_t)j, one, m15, m6, m29, m24) >> 9;
    if (v > bestv) { bestv = v; bestj = j; }
  }
  if (bestj < 0) bestv = 0u;          // lane had no candidate
  sv[t] = bestv; sj[t] = bestj;
  __syncthreads();
  for (int s = 128; s; s >>= 1) {
    if (t < s) {
      uint32_t ov = sv[t + s]; int oj = sj[t + s];
      if (oj >= 0 && (sj[t] < 0 || ov > sv[t] || (ov == sv[t] && oj < sj[t]))) {
        sv[t] = ov; sj[t] = oj;
      }
    }
    __syncthreads();
  }
  if (t == 0) g_neg[i] = (sj[0] >= 0) ? sj[0] : 0;
}

__global__ void k_mu(const float* __restrict__ F) {
  int c = threadIdx.x;
  int r0 = blockIdx.x * 128;
  float s = 0.f;
  for (int r = 0; r < 128; r++) s += F[(size_t)(r0 + r) * DD + c];
  atomicAdd(&g_musum[c], s);
}

// S = F^T F, upper-triangle 64x64 block tiles (36), split-K (z=8), FFMA2.
__global__ void k_syrk(const float* __restrict__ F) {
  __shared__ float As[16][64];
  __shared__ float Bs[16][64];
  int rem = blockIdx.x, bi = 0;
  while (rem >= 8 - bi) { rem -= 8 - bi; bi++; }
  int bj = bi + rem;
  int i0 = bi * 64, j0 = bj * 64;
  int kb = blockIdx.z * 1024;
  int t = threadIdx.x;
  int tx = t & 15, ty = t >> 4;
  unsigned long long acc2[4][2];
#pragma unroll
  for (int u = 0; u < 4; u++) { acc2[u][0] = 0ull; acc2[u][1] = 0ull; }

  for (int k = kb; k < kb + 1024; k += 16) {
#pragma unroll
    for (int r = 0; r < 4; r++) {
      int e = t + 256 * r, kk = e >> 6, c = e & 63;
      As[kk][c] = F[(size_t)(k + kk) * DD + i0 + c];
      Bs[kk][c] = F[(size_t)(k + kk) * DD + j0 + c];
    }
    __syncthreads();
#pragma unroll
    for (int kk = 0; kk < 16; kk++) {
      unsigned long long aa[4], bb[2];
      const unsigned long long* bp = (const unsigned long long*)&Bs[kk][tx * 4];
      bb[0] = bp[0]; bb[1] = bp[1];
#pragma unroll
      for (int u = 0; u < 4; u++) aa[u] = pack2(As[kk][ty * 4 + u]);
#pragma unroll
      for (int u = 0; u < 4; u++) {
        ffma2(acc2[u][0], aa[u], bb[0]);
        ffma2(acc2[u][1], aa[u], bb[1]);
      }
    }
    __syncthreads();
  }
#pragma unroll
  for (int u = 0; u < 4; u++) {
#pragma unroll
    for (int v2 = 0; v2 < 2; v2++) {
      U64F2 cv; cv.u = acc2[u][v2];
      size_t row = (size_t)(i0 + ty * 4 + u) * DD + j0 + tx * 4 + v2 * 2;
      atomicAdd(&g_S[row],     cv.f.x);
      atomicAdd(&g_S[row + 1], cv.f.y);
    }
  }
}

__global__ void k_makeG() {
  int i = blockIdx.x, j = threadIdx.x;
  const float invB = 1.0f / (float)BB;
  float mui = g_musum[i] * invB;
  float muj = g_musum[j] * invB;
  float s = (i <= j) ? g_S[(size_t)i * DD + j] : g_S[(size_t)j * DD + i];
  float v = s * invB - mui * muj + (i == j ? 1.0f : 0.0f);
  g_G[(size_t)i * DD + j] = v;
}

// H = F * G  (8192x512 @ 512x512), FFMA2 inner loop.
__global__ void k_gemmH(const float* __restrict__ F) {
  __shared__ float As[16][65];
  __shared__ float Bs[16][64];
  int m0 = blockIdx.x * 64, n0 = blockIdx.y * 64;
  int t = threadIdx.x, tx = t & 15, ty = t >> 4;
  unsigned long long acc2[4][2];
#pragma unroll
  for (int u = 0; u < 4; u++) { acc2[u][0] = 0ull; acc2[u][1] = 0ull; }

  for (int k = 0; k < DD; k += 16) {
#pragma unroll
    for (int r = 0; r < 4; r++) {
      int e = t + 256 * r;
      int kk = e & 15, mm = e >> 4;
      As[kk][mm] = F[(size_t)(m0 + mm) * DD + k + kk];
    }
#pragma unroll
    for (int r = 0; r < 4; r++) {
      int e = t + 256 * r, kk = e >> 6, c = e & 63;
      Bs[kk][c] = g_G[(size_t)(k + kk) * DD + n0 + c];
    }
    __syncthreads();
#pragma unroll
    for (int kk = 0; kk < 16; kk++) {
      unsigned long long aa[4], bb[2];
      const unsigned long long* bp = (const unsigned long long*)&Bs[kk][tx * 4];
      bb[0] = bp[0]; bb[1] = bp[1];
#pragma unroll
      for (int u = 0; u < 4; u++) aa[u] = pack2(As[kk][ty * 4 + u]);
#pragma unroll
      for (int u = 0; u < 4; u++) {
        ffma2(acc2[u][0], aa[u], bb[0]);
        ffma2(acc2[u][1], aa[u], bb[1]);
      }
    }
    __syncthreads();
  }
#pragma unroll
  for (int u = 0; u < 4; u++) {
    U64F2 lo, hi; lo.u = acc2[u][0]; hi.u = acc2[u][1];
    float4 o; o.x = lo.f.x; o.y = lo.f.y; o.z = hi.f.x; o.w = hi.f.y;
    *(float4*)&g_H[(size_t)(m0 + ty * 4 + u) * DD + n0 + tx * 4] = o;
  }
}

__global__ void k_q(const float* __restrict__ F) {
  int w = (blockIdx.x * blockDim.x + threadIdx.x) >> 5;
  int lane = threadIdx.x & 31;
  if (w >= BB) return;
  const float* f = F + (size_t)w * DD;
  const float* h = g_H + (size_t)w * DD;
  float s = 0.f;
  for (int c = lane; c < DD; c += 32) s += f[c] * h[c];
  for (int o = 16; o; o >>= 1) s += __shfl_down_sync(0xffffffffu, s, o);
  if (lane == 0) g_q[w] = s;
}

__global__ void k_loss(const float* __restrict__ F) {
  __shared__ float rp[128], rn[128];
  int i = blockIdx.x, t = threadIdx.x;
  int p = g_pos[i], n = g_neg[i];
  float sp = 0.f, sn = 0.f;
  const float* f  = F   + (size_t)i * DD;
  const float* hp = g_H + (size_t)p * DD;
  const float* hn = g_H + (size_t)n * DD;
  for (int c = t; c < DD; c += 128) {
    float fv = f[c];
    sp += fv * hp[c];
    sn += fv * hn[c];
  }
  rp[t] = sp; rn[t] = sn;
  __syncthreads();
  for (int s = 64; s; s >>= 1) {
    if (t < s) { rp[t] += rp[t + s]; rn[t] += rn[t + s]; }
    __syncthreads();
  }
  if (t == 0) {
    int lab = g_lab[i];
    int cnt = g_cnt[lab];
    bool valid = (cnt >= 2) && (cnt < BB);
    if (valid) {
      float dp = sqrtf(g_q[i] + g_q[p] - 2.0f * rp[0] + 1e-8f);
      float dn = sqrtf(g_q[i] + g_q[n] - 2.0f * rn[0] + 1e-8f);
      float per = fmaxf(dp - dn + 1.0f, 0.0f);
      atomicAdd(&g_acc[0], per);
      atomicAdd(&g_acc[1], 1.0f);
    }
  }
}

__global__ void k_final(float* __restrict__ out) {
  out[0] = g_acc[0] / fmaxf(g_acc[1], 1.0f);
}

// ---------------------------------------------------------------------------
extern "C" void kernel_launch(void* const* d_in, const int* in_sizes, int n_in,
                              void* d_out, int out_size) {
  const float* F = (const float*)d_in[0];
  const void*  L = d_in[1];
  float* out = (float*)d_out;

  static cudaStream_t s_samp = nullptr;
  static cudaEvent_t  ev_fork = nullptr, ev_join = nullptr;
  if (s_samp == nullptr) {
    cudaStreamCreateWithFlags(&s_samp, cudaStreamNonBlocking);
    cudaEventCreateWithFlags(&ev_fork, cudaEventDisableTiming);
    cudaEventCreateWithFlags(&ev_join, cudaEventDisableTiming);
  }

  // opaque 1: runtime kernel parameter — ptxas cannot fold the IMADs away
  const uint32_t one = (uint32_t)(n_in > 0);

  cudaEventRecord(ev_fork, 0);
  cudaStreamWaitEvent(s_samp, ev_fork, 0);
  k_labels<<<1, 1024, 0, s_samp>>>(L);
  k_offsets<<<1, 32, 0, s_samp>>>();
  k_scatter<<<32, 256, 0, s_samp>>>();
  k_pos<<<BB / 8, 256, 0, s_samp>>>(one);
  k_neg<<<BB, 256, 0, s_samp>>>(one);
  cudaEventRecord(ev_join, s_samp);

  k_zero<<<256, 256>>>();
  k_mu<<<64, 512>>>(F);
  {
    dim3 g(36, 1, 8);
    k_syrk<<<g, 256>>>(F);
  }
  k_makeG<<<512, 512>>>();
  {
    dim3 g(128, 8);
    k_gemmH<<<g, 256>>>(F);
  }
  k_q<<<BB / 8, 256>>>(F);

  cudaStreamWaitEvent(0, ev_join, 0);
  k_loss<<<BB, 128>>>(F);
  k_final<<<1, 1>>>(out);
}

// round 9
// speedup vs baseline: 1.0919x; 1.0919x over previous
#include <cuda_runtime.h>
#include <stdint.h>
#include <math.h>

// ---------------------------------------------------------------------------
// TripletLossWithCurvature: B=8192, D=512, classes<100
// Bit-exact JAX Threefry-2x32 (partitionable mode).
// R9: revert R8's pipe-rebalance (regressed); plain-C Threefry + 4-way ILP
// batching in k_neg (4 independent chains per thread per iteration),
// branchless masking. Compile-time subkeys kept. FFMA2 GEMMs kept.
// ---------------------------------------------------------------------------
#define BB 8192
#define DD 512
#define NCLS 128

__device__ float g_S[DD*DD];
__device__ float g_G[DD*DD];
__device__ float g_H[BB*DD];
__device__ float g_q[BB];
__device__ float g_musum[DD];
__device__ int   g_lab[BB];
__device__ unsigned char g_lab8[BB];
__device__ int   g_cnt[NCLS];
__device__ int   g_off[NCLS];
__device__ int   g_fill[NCLS];
__device__ int   g_list[BB];
__device__ int   g_pos[BB];
__device__ int   g_neg[BB];
__device__ float g_acc[2];

// ---------------------------------------------------------------------------
// Packed fp32 helpers (exact per-lane IEEE fp32)
// ---------------------------------------------------------------------------
__device__ __forceinline__ void ffma2(unsigned long long &acc,
                                      unsigned long long a2,
                                      unsigned long long b2) {
  asm("fma.rn.f32x2 %0, %1, %2, %0;" : "+l"(acc) : "l"(a2), "l"(b2));
}
__device__ __forceinline__ unsigned long long pack2(float x) {
  unsigned long long r;
  unsigned int xi = __float_as_uint(x);
  asm("mov.b64 %0, {%1, %1};" : "=l"(r) : "r"(xi));
  return r;
}
union U64F2 { unsigned long long u; float2 f; };

// ---------------------------------------------------------------------------
// Threefry-2x32, 20 rounds — plain C (ptxas schedules best on its own)
// ---------------------------------------------------------------------------
__device__ __forceinline__ void tf_block(uint32_t k0, uint32_t k1,
                                         uint32_t &x0, uint32_t &x1) {
  uint32_t ks2 = k0 ^ k1 ^ 0x1BD11BDAu;
  x0 += k0; x1 += k1;
#define TF_ROT(x,r) (((x) << (r)) | ((x) >> (32 - (r))))
#define TF_RND(r) { x0 += x1; x1 = TF_ROT(x1, r); x1 ^= x0; }
  TF_RND(13) TF_RND(15) TF_RND(26) TF_RND(6)
  x0 += k1;  x1 += ks2 + 1u;
  TF_RND(17) TF_RND(29) TF_RND(16) TF_RND(24)
  x0 += ks2; x1 += k0 + 2u;
  TF_RND(13) TF_RND(15) TF_RND(26) TF_RND(6)
  x0 += k0;  x1 += k1 + 3u;
  TF_RND(17) TF_RND(29) TF_RND(16) TF_RND(24)
  x0 += k1;  x1 += ks2 + 4u;
  TF_RND(13) TF_RND(15) TF_RND(26) TF_RND(6)
  x0 += ks2; x1 += k0 + 5u;
#undef TF_RND
#undef TF_ROT
}

__device__ __forceinline__ uint32_t draw_bits(uint32_t k0, uint32_t k1, uint32_t p) {
  uint32_t x0 = 0u, x1 = p;
  tf_block(k0, k1, x0, x1);
  return x0 ^ x1;
}

// Compile-time subkey derivation: split(key(42)) blocks on counts 0/1.
struct K2 { uint32_t a, b; };
constexpr uint32_t c_rotl(uint32_t x, int r) {
  return (x << r) | (x >> (32 - r));
}
constexpr K2 tf_pair(uint32_t k0, uint32_t k1, uint32_t c0, uint32_t c1) {
  uint32_t ks2 = k0 ^ k1 ^ 0x1BD11BDAu;
  uint32_t x0 = c0 + k0, x1 = c1 + k1;
#define CR(r) x0 += x1; x1 = c_rotl(x1, r); x1 ^= x0;
  CR(13) CR(15) CR(26) CR(6)
  x0 += k1;  x1 += ks2 + 1u;
  CR(17) CR(29) CR(16) CR(24)
  x0 += ks2; x1 += k0 + 2u;
  CR(13) CR(15) CR(26) CR(6)
  x0 += k0;  x1 += k1 + 3u;
  CR(17) CR(29) CR(16) CR(24)
  x0 += k1;  x1 += ks2 + 4u;
  CR(13) CR(15) CR(26) CR(6)
  x0 += ks2; x1 += k0 + 5u;
#undef CR
  return K2{x0, x1};
}
constexpr K2 KP = tf_pair(0u, 42u, 0u, 0u);   // positive-sampling key
constexpr K2 KN = tf_pair(0u, 42u, 0u, 1u);   // negative-sampling key

// ---------------------------------------------------------------------------
// Kernels
// ---------------------------------------------------------------------------
__global__ void k_zero() {
  int idx = blockIdx.x * blockDim.x + threadIdx.x;
  int stride = gridDim.x * blockDim.x;
  for (int i = idx; i < DD*DD; i += stride) g_S[i] = 0.f;
  if (idx < DD) g_musum[idx] = 0.f;
}

__global__ void k_labels(const void* __restrict__ lraw) {
  __shared__ int s_is64;
  if (threadIdx.x < NCLS) g_cnt[threadIdx.x] = 0;
  if (threadIdx.x < 2)    g_acc[threadIdx.x] = 0.f;
  if (threadIdx.x == 0)   s_is64 = 1;
  __syncthreads();
  const int* w = (const int*)lraw;
  int any = 0;
  for (int k = threadIdx.x; k < 4096; k += 1024)
    if (w[2*k + 1] != 0) any = 1;
  if (any) s_is64 = 0;
  __syncthreads();
  int is64 = s_is64;
  for (int i = threadIdx.x; i < BB; i += 1024) {
    int lab = is64 ? (int)(((const long long*)lraw)[i]) : w[i];
    if (lab < 0) lab = 0;
    if (lab >= NCLS) lab = NCLS - 1;
    g_lab[i]  = lab;
    g_lab8[i] = (unsigned char)lab;
    atomicAdd(&g_cnt[lab], 1);
  }
}

__global__ void k_offsets() {
  if (threadIdx.x == 0 && blockIdx.x == 0) {
    int acc = 0;
    for (int c = 0; c < NCLS; c++) { g_off[c] = acc; g_fill[c] = acc; acc += g_cnt[c]; }
  }
}

__global__ void k_scatter() {
  int i = blockIdx.x * blockDim.x + threadIdx.x;
  if (i < BB) {
    int lab = g_lab[i];
    int p = atomicAdd(&g_fill[lab], 1);
    g_list[p] = i;
  }
}

// Positive sampling: one warp per row; g_list unsorted -> full tie-break.
__global__ void k_pos() {
  int w = (blockIdx.x * blockDim.x + threadIdx.x) >> 5;
  int lane = threadIdx.x & 31;
  if (w >= BB) return;
  int i = w;
  int lab = g_lab[i];
  int off = g_off[lab], cnt = g_cnt[lab];
  uint32_t base = (uint32_t)i * (uint32_t)BB;
  uint32_t bestv = 0u; int bestj = 0; int any = 0;
  for (int c = lane; c < cnt; c += 32) {
    int j = g_list[off + c];
    if (j == i) continue;
    uint32_t v = draw_bits(KP.a, KP.b, base + (uint32_t)j) >> 9;
    if (!any || v > bestv || (v == bestv && j < bestj)) { any = 1; bestv = v; bestj = j; }
  }
  for (int o = 16; o; o >>= 1) {
    uint32_t ov = __shfl_down_sync(0xffffffffu, bestv, o);
    int      oj = __shfl_down_sync(0xffffffffu, bestj, o);
    int      oa = __shfl_down_sync(0xffffffffu, any,  o);
    if (oa && (!any || ov > bestv || (ov == bestv && oj < bestj))) {
      any = 1; bestv = ov; bestj = oj;
    }
  }
  if (lane == 0) g_pos[i] = bestj;
}

// Negative sampling: one block per row; 4 independent Threefry chains per
// thread per iteration (ILP), branchless masking. Per-thread candidates are
// visited in ascending j, so strict > preserves first-occurrence argmax.
__global__ void k_neg() {
  __shared__ unsigned char slab[BB];
  __shared__ uint32_t sv[256];
  __shared__ int sj[256];
  int i = blockIdx.x, t = threadIdx.x;
  {
    const uint32_t* l4 = (const uint32_t*)g_lab8;
    uint32_t* s4 = (uint32_t*)slab;
    for (int j = t; j < BB / 4; j += 256) s4[j] = l4[j];
  }
  __syncthreads();
  unsigned char mylab = slab[i];
  uint32_t base = (uint32_t)i * (uint32_t)BB;
  uint32_t bestv = 0u; int bestj = -1;
#pragma unroll
  for (int s = 0; s < 8; s++) {
    int j0 = t + s * 1024;
    int j1 = j0 + 256, j2 = j0 + 512, j3 = j0 + 768;
    // 4 independent chains -> ptxas interleaves, hiding the 4-cyc dep chain
    uint32_t d0 = draw_bits(KN.a, KN.b, base + (uint32_t)j0);
    uint32_t d1 = draw_bits(KN.a, KN.b, base + (uint32_t)j1);
    uint32_t d2 = draw_bits(KN.a, KN.b, base + (uint32_t)j2);
    uint32_t d3 = draw_bits(KN.a, KN.b, base + (uint32_t)j3);
    uint32_t v0 = (slab[j0] == mylab) ? 0u : (d0 >> 9);
    uint32_t v1 = (slab[j1] == mylab) ? 0u : (d1 >> 9);
    uint32_t v2 = (slab[j2] == mylab) ? 0u : (d2 >> 9);
    uint32_t v3 = (slab[j3] == mylab) ? 0u : (d3 >> 9);
    if (v0 > bestv) { bestv = v0; bestj = j0; }
    if (v1 > bestv) { bestv = v1; bestj = j1; }
    if (v2 > bestv) { bestv = v2; bestj = j2; }
    if (v3 > bestv) { bestv = v3; bestj = j3; }
  }
  // bestv==0 => no candidate beat 0; treat as none (P ~ 2^-23 per masked-out
  // candidate that a real one drew exactly 0 AND nothing else was larger —
  // vanishes after the cross-thread reduce over 8100 candidates).
  sv[t] = bestv; sj[t] = bestj;
  __syncthreads();
  for (int s = 128; s; s >>= 1) {
    if (t < s) {
      uint32_t ov = sv[t + s]; int oj = sj[t + s];
      if (oj >= 0 && (sj[t] < 0 || ov > sv[t] || (ov == sv[t] && oj < sj[t]))) {
        sv[t] = ov; sj[t] = oj;
      }
    }
    __syncthreads();
  }
  if (t == 0) g_neg[i] = (sj[0] >= 0) ? sj[0] : 0;
}

__global__ void k_mu(const float* __restrict__ F) {
  int c = threadIdx.x;
  int r0 = blockIdx.x * 128;
  float s = 0.f;
  for (int r = 0; r < 128; r++) s += F[(size_t)(r0 + r) * DD + c];
  atomicAdd(&g_musum[c], s);
}

// S = F^T F, upper-triangle 64x64 block tiles (36), split-K (z=8), FFMA2.
__global__ void k_syrk(const float* __restrict__ F) {
  __shared__ float As[16][64];
  __shared__ float Bs[16][64];
  int rem = blockIdx.x, bi = 0;
  while (rem >= 8 - bi) { rem -= 8 - bi; bi++; }
  int bj = bi + rem;
  int i0 = bi * 64, j0 = bj * 64;
  int kb = blockIdx.z * 1024;
  int t = threadIdx.x;
  int tx = t & 15, ty = t >> 4;
  unsigned long long acc2[4][2];
#pragma unroll
  for (int u = 0; u < 4; u++) { acc2[u][0] = 0ull; acc2[u][1] = 0ull; }

  for (int k = kb; k < kb + 1024; k += 16) {
#pragma unroll
    for (int r = 0; r < 4; r++) {
      int e = t + 256 * r, kk = e >> 6, c = e & 63;
      As[kk][c] = F[(size_t)(k + kk) * DD + i0 + c];
      Bs[kk][c] = F[(size_t)(k + kk) * DD + j0 + c];
    }
    __syncthreads();
#pragma unroll
    for (int kk = 0; kk < 16; kk++) {
      unsigned long long aa[4], bb[2];
      const unsigned long long* bp = (const unsigned long long*)&Bs[kk][tx * 4];
      bb[0] = bp[0]; bb[1] = bp[1];
#pragma unroll
      for (int u = 0; u < 4; u++) aa[u] = pack2(As[kk][ty * 4 + u]);
#pragma unroll
      for (int u = 0; u < 4; u++) {
        ffma2(acc2[u][0], aa[u], bb[0]);
        ffma2(acc2[u][1], aa[u], bb[1]);
      }
    }
    __syncthreads();
  }
#pragma unroll
  for (int u = 0; u < 4; u++) {
#pragma unroll
    for (int v2 = 0; v2 < 2; v2++) {
      U64F2 cv; cv.u = acc2[u][v2];
      size_t row = (size_t)(i0 + ty * 4 + u) * DD + j0 + tx * 4 + v2 * 2;
      atomicAdd(&g_S[row],     cv.f.x);
      atomicAdd(&g_S[row + 1], cv.f.y);
    }
  }
}

__global__ void k_makeG() {
  int i = blockIdx.x, j = threadIdx.x;
  const float invB = 1.0f / (float)BB;
  float mui = g_musum[i] * invB;
  float muj = g_musum[j] * invB;
  float s = (i <= j) ? g_S[(size_t)i * DD + j] : g_S[(size_t)j * DD + i];
  float v = s * invB - mui * muj + (i == j ? 1.0f : 0.0f);
  g_G[(size_t)i * DD + j] = v;
}

// H = F * G  (8192x512 @ 512x512), FFMA2 inner loop.
__global__ void k_gemmH(const float* __restrict__ F) {
  __shared__ float As[16][65];
  __shared__ float Bs[16][64];
  int m0 = blockIdx.x * 64, n0 = blockIdx.y * 64;
  int t = threadIdx.x, tx = t & 15, ty = t >> 4;
  unsigned long long acc2[4][2];
#pragma unroll
  for (int u = 0; u < 4; u++) { acc2[u][0] = 0ull; acc2[u][1] = 0ull; }

  for (int k = 0; k < DD; k += 16) {
#pragma unroll
    for (int r = 0; r < 4; r++) {
      int e = t + 256 * r;
      int kk = e & 15, mm = e >> 4;
      As[kk][mm] = F[(size_t)(m0 + mm) * DD + k + kk];
    }
#pragma unroll
    for (int r = 0; r < 4; r++) {
      int e = t + 256 * r, kk = e >> 6, c = e & 63;
      Bs[kk][c] = g_G[(size_t)(k + kk) * DD + n0 + c];
    }
    __syncthreads();
#pragma unroll
    for (int kk = 0; kk < 16; kk++) {
      unsigned long long aa[4], bb[2];
      const unsigned long long* bp = (const unsigned long long*)&Bs[kk][tx * 4];
      bb[0] = bp[0]; bb[1] = bp[1];
#pragma unroll
      for (int u = 0; u < 4; u++) aa[u] = pack2(As[kk][ty * 4 + u]);
#pragma unroll
      for (int u = 0; u < 4; u++) {
        ffma2(acc2[u][0], aa[u], bb[0]);
        ffma2(acc2[u][1], aa[u], bb[1]);
      }
    }
    __syncthreads();
  }
#pragma unroll
  for (int u = 0; u < 4; u++) {
    U64F2 lo, hi; lo.u = acc2[u][0]; hi.u = acc2[u][1];
    float4 o; o.x = lo.f.x; o.y = lo.f.y; o.z = hi.f.x; o.w = hi.f.y;
    *(float4*)&g_H[(size_t)(m0 + ty * 4 + u) * DD + n0 + tx * 4] = o;
  }
}

__global__ void k_q(const float* __restrict__ F) {
  int w = (blockIdx.x * blockDim.x + threadIdx.x) >> 5;
  int lane = threadIdx.x & 31;
  if (w >= BB) return;
  const float* f = F + (size_t)w * DD;
  const float* h = g_H + (size_t)w * DD;
  float s = 0.f;
  for (int c = lane; c < DD; c += 32) s += f[c] * h[c];
  for (int o = 16; o; o >>= 1) s += __shfl_down_sync(0xffffffffu, s, o);
  if (lane == 0) g_q[w] = s;
}

__global__ void k_loss(const float* __restrict__ F) {
  __shared__ float rp[128], rn[128];
  int i = blockIdx.x, t = threadIdx.x;
  int p = g_pos[i], n = g_neg[i];
  float sp = 0.f, sn = 0.f;
  const float* f  = F   + (size_t)i * DD;
  const float* hp = g_H + (size_t)p * DD;
  const float* hn = g_H + (size_t)n * DD;
  for (int c = t; c < DD; c += 128) {
    float fv = f[c];
    sp += fv * hp[c];
    sn += fv * hn[c];
  }
  rp[t] = sp; rn[t] = sn;
  __syncthreads();
  for (int s = 64; s; s >>= 1) {
    if (t < s) { rp[t] += rp[t + s]; rn[t] += rn[t + s]; }
    __syncthreads();
  }
  if (t == 0) {
    int lab = g_lab[i];
    int cnt = g_cnt[lab];
    bool valid = (cnt >= 2) && (cnt < BB);
    if (valid) {
      float dp = sqrtf(g_q[i] + g_q[p] - 2.0f * rp[0] + 1e-8f);
      float dn = sqrtf(g_q[i] + g_q[n] - 2.0f * rn[0] + 1e-8f);
      float per = fmaxf(dp - dn + 1.0f, 0.0f);
      atomicAdd(&g_acc[0], per);
      atomicAdd(&g_acc[1], 1.0f);
    }
  }
}

__global__ void k_final(float* __restrict__ out) {
  out[0] = g_acc[0] / fmaxf(g_acc[1], 1.0f);
}

// ---------------------------------------------------------------------------
extern "C" void kernel_launch(void* const* d_in, const int* in_sizes, int n_in,
                              void* d_out, int out_size) {
  const float* F = (const float*)d_in[0];
  const void*  L = d_in[1];
  float* out = (float*)d_out;

  static cudaStream_t s_samp = nullptr;
  static cudaEvent_t  ev_fork = nullptr, ev_join = nullptr;
  if (s_samp == nullptr) {
    cudaStreamCreateWithFlags(&s_samp, cudaStreamNonBlocking);
    cudaEventCreateWithFlags(&ev_fork, cudaEventDisableTiming);
    cudaEventCreateWithFlags(&ev_join, cudaEventDisableTiming);
  }

  cudaEventRecord(ev_fork, 0);
  cudaStreamWaitEvent(s_samp, ev_fork, 0);
  k_labels<<<1, 1024, 0, s_samp>>>(L);
  k_offsets<<<1, 32, 0, s_samp>>>();
  k_scatter<<<32, 256, 0, s_samp>>>();
  k_pos<<<BB / 8, 256, 0, s_samp>>>();
  k_neg<<<BB, 256, 0, s_samp>>>();
  cudaEventRecord(ev_join, s_samp);

  k_zero<<<256, 256>>>();
  k_mu<<<64, 512>>>(F);
  {
    dim3 g(36, 1, 8);
    k_syrk<<<g, 256>>>(F);
  }
  k_makeG<<<512, 512>>>();
  {
    dim3 g(128, 8);
    k_gemmH<<<g, 256>>>(F);
  }
  k_q<<<BB / 8, 256>>>(F);

  cudaStreamWaitEvent(0, ev_join, 0);
  k_loss<<<BB, 128>>>(F);
  k_final<<<1, 1>>>(out);
}